// round 5
// baseline (speedup 1.0000x reference)
#include <cuda_runtime.h>
#include <math.h>

#define BATCH 32
#define CIN 512
#define HID 64
#define PLANE 4096            // floats per (b,c) plane
#define PLANE4 1024           // float4s per plane
#define NKNOT 12
#define NBASE 8
#define NPLANES (BATCH * CIN) // 16384
#define NGROUPS (NPLANES / 4) // 4096 groups of 4 planes

#define NBLOCKS 296
#define NTHREADS 512
#define NWARPS (NBLOCKS * (NTHREADS / 32))   // 4736
#define TOT_F4 (NPLANES * PLANE4)            // 16777216

// Scratch (no device allocations allowed)
__device__ float g_silu[BATCH * CIN];
__device__ float g_bases[BATCH * CIN * NBASE];
__device__ float g_h2silu[BATCH * HID];
__device__ float g_b2[BATCH * HID * NBASE];
__device__ float g_gate[BATCH * CIN];

__device__ unsigned int g_bar_count = 0;
__device__ volatile unsigned int g_bar_gen = 0;

__device__ __forceinline__ void grid_barrier() {
    __threadfence();
    __syncthreads();
    if (threadIdx.x == 0) {
        unsigned int gen = g_bar_gen;
        unsigned int old = atomicAdd(&g_bar_count, 1u);
        if (old == NBLOCKS - 1) {
            g_bar_count = 0;
            __threadfence();
            g_bar_gen = gen + 1;
        } else {
            while (g_bar_gen == gen) { __nanosleep(32); }
        }
        __threadfence();
    }
    __syncthreads();
}

__device__ __forceinline__ float siluf(float v) {
    return v / (1.0f + __expf(-v));
}

// Cox-de Boor, mirroring the reference recursion. 12 knots -> 8 order-3 bases.
__device__ __forceinline__ void bspline8(float x, const float* t, float* out) {
    float b[11];
#pragma unroll
    for (int j = 0; j < 11; j++)
        b[j] = (x >= t[j] && x < t[j + 1]) ? 1.0f : 0.0f;
#pragma unroll
    for (int k = 1; k <= 3; k++) {
#pragma unroll
        for (int j = 0; j < 10; j++) {
            if (j <= 10 - k) {
                float left  = (x - t[j]) / (t[j + k] - t[j]) * b[j];
                float right = (t[j + k + 1] - x) / (t[j + k + 1] - t[j + 1]) * b[j + 1];
                b[j] = left + right;
            }
        }
    }
#pragma unroll
    for (int j = 0; j < NBASE; j++) out[j] = b[j];
}

__global__ void __launch_bounds__(NTHREADS, 2) kanse_persistent(
    const float4* __restrict__ x,
    const float* __restrict__ grid1, const float* __restrict__ bw1,
    const float* __restrict__ sw1,  const float* __restrict__ sc1,
    const float* __restrict__ grid2, const float* __restrict__ bw2,
    const float* __restrict__ sw2,  const float* __restrict__ sc2,
    float4* __restrict__ out) {

    const int lane = threadIdx.x & 31;
    const int wid  = threadIdx.x >> 5;          // 0..15
    const int w    = blockIdx.x * (NTHREADS / 32) + wid;

    __shared__ float sh_part[16];

    // ===== Phase 1: plane means (4 warps/plane, 4 planes/block-iter) =====
    for (int group = blockIdx.x; group < NGROUPS; group += NBLOCKS) {
        const int plane_in_grp = wid >> 2;       // 0..3
        const int quarter      = wid & 3;        // 0..3
        const int plane = group * 4 + plane_in_grp;
        const float4* p = x + (size_t)plane * PLANE4 + quarter * 256;

        float4 r[8];
#pragma unroll
        for (int u = 0; u < 8; u++)
            r[u] = __ldcs(&p[u * 32 + lane]);
        float sum = 0.0f;
#pragma unroll
        for (int u = 0; u < 8; u++)
            sum += (r[u].x + r[u].y) + (r[u].z + r[u].w);
#pragma unroll
        for (int off = 16; off >= 1; off >>= 1)
            sum += __shfl_xor_sync(0xffffffffu, sum, off);
        if (lane == 0) sh_part[wid] = sum;
        __syncthreads();

        if (threadIdx.x < 4) {
            const int pl = group * 4 + threadIdx.x;
            float tot = sh_part[threadIdx.x * 4]     + sh_part[threadIdx.x * 4 + 1]
                      + sh_part[threadIdx.x * 4 + 2] + sh_part[threadIdx.x * 4 + 3];
            float m = tot * (1.0f / (float)PLANE);
            if (isnan(m)) m = 0.0f;
            m = fminf(fmaxf(m, -3.402823466e38f), 3.402823466e38f);
            const int c = pl & (CIN - 1);
            float t[NKNOT];
#pragma unroll
            for (int j = 0; j < NKNOT; j++) t[j] = grid1[c * NKNOT + j];
            float bb[NBASE];
            bspline8(m, t, bb);
#pragma unroll
            for (int k = 0; k < NBASE; k++) g_bases[pl * NBASE + k] = bb[k];
            g_silu[pl] = siluf(m);
        }
        __syncthreads();
    }

    grid_barrier();

    // ===== Phase 2a: layer 1 (warp per (b,o)) =====
    if (w < BATCH * HID) {
        const int b = w >> 6;
        const int o = w & (HID - 1);
        const float4* sw4 = (const float4*)(sw1 + (size_t)o * CIN * NBASE);
        const float4* ba4 = (const float4*)(g_bases + (size_t)b * CIN * NBASE);
        const float*  sl  = g_silu + b * CIN;
        const float*  bwr = bw1 + o * CIN;
        const float*  scr = sc1 + o * CIN;

        float acc = 0.0f;
#pragma unroll
        for (int it = 0; it < 16; it++) {
            int c = lane + 32 * it;
            float4 wa = sw4[c * 2];
            float4 wb = sw4[c * 2 + 1];
            float4 ca = ba4[c * 2];
            float4 cb = ba4[c * 2 + 1];
            float sp = ca.x * wa.x + ca.y * wa.y + ca.z * wa.z + ca.w * wa.w
                     + cb.x * wb.x + cb.y * wb.y + cb.z * wb.z + cb.w * wb.w;
            acc += sl[c] * bwr[c] + sp * scr[c];
        }
#pragma unroll
        for (int off = 16; off >= 1; off >>= 1)
            acc += __shfl_xor_sync(0xffffffffu, acc, off);

        if (lane == 0) {
            float h = siluf(acc);
            g_h2silu[b * HID + o] = siluf(h);
            float t[NKNOT];
#pragma unroll
            for (int j = 0; j < NKNOT; j++) t[j] = grid2[o * NKNOT + j];
            float bb2[NBASE];
            bspline8(h, t, bb2);
#pragma unroll
            for (int k = 0; k < NBASE; k++)
                g_b2[(b * HID + o) * NBASE + k] = bb2[k];
        }
    }

    grid_barrier();

    // ===== Phase 2b: layer 2 + sigmoid (warp per (b,c)) =====
    for (int t = w; t < BATCH * CIN; t += NWARPS) {
        const int b = t >> 9;
        const int c = t & (CIN - 1);
        const int j0 = lane * 2;
        const float4* sw4 = (const float4*)(sw2 + (size_t)c * HID * NBASE);
        const float4* b24 = (const float4*)(g_b2 + (size_t)b * HID * NBASE);

        float4 w0 = sw4[j0 * 2];
        float4 w1 = sw4[j0 * 2 + 1];
        float4 w2 = sw4[j0 * 2 + 2];
        float4 w3 = sw4[j0 * 2 + 3];
        float4 c0 = b24[j0 * 2];
        float4 c1 = b24[j0 * 2 + 1];
        float4 c2 = b24[j0 * 2 + 2];
        float4 c3 = b24[j0 * 2 + 3];
        float sp0 = c0.x * w0.x + c0.y * w0.y + c0.z * w0.z + c0.w * w0.w
                  + c1.x * w1.x + c1.y * w1.y + c1.z * w1.z + c1.w * w1.w;
        float sp1 = c2.x * w2.x + c2.y * w2.y + c2.z * w2.z + c2.w * w2.w
                  + c3.x * w3.x + c3.y * w3.y + c3.z * w3.z + c3.w * w3.w;
        float2 bw = *(const float2*)(bw2 + c * HID + j0);
        float2 sc = *(const float2*)(sc2 + c * HID + j0);
        float2 h2 = *(const float2*)(g_h2silu + b * HID + j0);
        float acc = h2.x * bw.x + sp0 * sc.x + h2.y * bw.y + sp1 * sc.y;
#pragma unroll
        for (int off = 16; off >= 1; off >>= 1)
            acc += __shfl_xor_sync(0xffffffffu, acc, off);
        if (lane == 0)
            g_gate[t] = 1.0f / (1.0f + __expf(-acc));
    }

    grid_barrier();

    // ===== Phase 3: out = x * gate (flat grid-stride, 4-way unroll) =====
    {
        const int tid = blockIdx.x * NTHREADS + threadIdx.x;
        const int stride = NBLOCKS * NTHREADS;          // 151552
        // TOT_F4 / stride = 110.7 -> loop with 4-way unrolled body
        int idx = tid;
        for (; idx + 3 * stride < TOT_F4; idx += 4 * stride) {
            int i0 = idx, i1 = idx + stride, i2 = idx + 2 * stride, i3 = idx + 3 * stride;
            float4 v0 = __ldcs(&x[i0]);
            float4 v1 = __ldcs(&x[i1]);
            float4 v2 = __ldcs(&x[i2]);
            float4 v3 = __ldcs(&x[i3]);
            float g0 = g_gate[i0 >> 10];
            float g1 = g_gate[i1 >> 10];
            float g2 = g_gate[i2 >> 10];
            float g3 = g_gate[i3 >> 10];
            v0.x *= g0; v0.y *= g0; v0.z *= g0; v0.w *= g0;
            v1.x *= g1; v1.y *= g1; v1.z *= g1; v1.w *= g1;
            v2.x *= g2; v2.y *= g2; v2.z *= g2; v2.w *= g2;
            v3.x *= g3; v3.y *= g3; v3.z *= g3; v3.w *= g3;
            __stcs(&out[i0], v0);
            __stcs(&out[i1], v1);
            __stcs(&out[i2], v2);
            __stcs(&out[i3], v3);
        }
        for (; idx < TOT_F4; idx += stride) {
            float4 v = __ldcs(&x[idx]);
            float g = g_gate[idx >> 10];
            v.x *= g; v.y *= g; v.z *= g; v.w *= g;
            __stcs(&out[idx], v);
        }
    }
}

extern "C" void kernel_launch(void* const* d_in, const int* in_sizes, int n_in,
                              void* d_out, int out_size) {
    const float* x     = (const float*)d_in[0];
    const float* grid1 = (const float*)d_in[1];
    const float* bw1   = (const float*)d_in[2];
    const float* sw1   = (const float*)d_in[3];
    const float* sc1   = (const float*)d_in[4];
    const float* grid2 = (const float*)d_in[5];
    const float* bw2   = (const float*)d_in[6];
    const float* sw2   = (const float*)d_in[7];
    const float* sc2   = (const float*)d_in[8];
    float* out = (float*)d_out;

    kanse_persistent<<<NBLOCKS, NTHREADS>>>(
        (const float4*)x, grid1, bw1, sw1, sc1,
        grid2, bw2, sw2, sc2, (float4*)out);
}